// round 7
// baseline (speedup 1.0000x reference)
#include <cuda_runtime.h>
#include <cstdint>

// Problem constants: R_MAX=32, S_MAX=2, C_Z=128, IN_FEATS=139
#define C_Z      128
#define IN_FEATS 139

// Global fused table layout (rows of 128 floats):
//   [0,66)    a rows:    Wt[dres]
//   [66,132)  b rows:    Wt[66+dtok]
//   [132,138) c rows:    ec<5 ? Wt[132]+Wt[133+ec] : Wt[138]
//   [138,144) bc rows:   b_sent + c_ec              (b_sent = Wt[131])
//   [144,150) abc rows:  a_sent + b_sent + c_ec     (a_sent = Wt[65])
//   [150,156) a32c rows: a[32] + c_ec               (case ri==rj: dres==32)
#define GROW_B    66
#define GTAB_ROWS 156

// Shared-memory table (a rows as-is; fused rows at global_row - 72):
//   [0,66) a | [66,72) bc | [72,78) abc | [78,84) a32c
#define S_A     0
#define S_BC    66
#define S_ABC   72
#define S_A32C  78
#define S_ROWS  84

#define N_MAX   1024

// pk flag bits
#define PK_TWO  (1u << 14)   // add second smem row r1
#define PK_GB   (1u << 15)   // add global b[dtok] row (rare ri==rj case)

__device__ float g_tab[GTAB_ROWS * C_Z];

// ---------------------------------------------------------------------------
// Pre-kernel: build fused table. W: [C_Z, IN_FEATS] row-major,
// Wt[f][c] = W[c*IN_FEATS + f].
// ---------------------------------------------------------------------------
__global__ void build_tables_kernel(const float* __restrict__ W) {
    int r = blockIdx.x;          // 0..155
    int c = threadIdx.x;         // 0..127
    const float* wc = W + (size_t)c * IN_FEATS;

    float a_sent = wc[65];
    float b_sent = wc[131];
    float a32    = wc[32];

    float v;
    if (r < 132) {
        v = wc[r];                                   // a rows, b rows
    } else {
        int k = (r - 132) % 6;                       // ec class
        float ck = (k < 5) ? (wc[132] + wc[133 + k]) : wc[138];
        if      (r < 138) v = ck;                    // c rows
        else if (r < 144) v = b_sent + ck;           // bc rows
        else if (r < 150) v = a_sent + b_sent + ck;  // abc rows
        else              v = a32 + ck;              // a32c rows
    }
    g_tab[r * C_Z + c] = v;
}

// ---------------------------------------------------------------------------
// pk computation for one (i, j) pair.
// pk: r0(7b) | r1(7b)<<7 | TWO<<14 | GB<<15 | dtok<<16
// ---------------------------------------------------------------------------
__device__ __forceinline__ unsigned make_pk(int ai, int ri, int ei, int si, int ti,
                                            int aj, int rj, int ej, int sj, int tj) {
    int ec = (ei == ej) ? min(max(si - sj + 2, 0), 4) : 5;
    if (ai != aj) {
        return (unsigned)(S_ABC + ec);                       // 1 row
    } else if (ri != rj) {
        int dres = min(max(ri - rj + 32, 0), 64);
        return (unsigned)(S_A + dres)
             | ((unsigned)(S_BC + ec) << 7) | PK_TWO;        // 2 rows
    } else {
        // dres == 32 exactly; a[32] folded into a32c[ec]; b row from global.
        int dtok = min(max(ti - tj + 32, 0), 64);
        return (unsigned)(S_A32C + ec)
             | PK_GB | ((unsigned)dtok << 16);               // 1 row + global
    }
}

// ---------------------------------------------------------------------------
// Main kernel: one block per TWO query rows (i0 = 2*bid, i1 = 2*bid+1);
// 256 threads = 8 warps; grid = N/2 = 512 -> single wave at 4 CTAs/SM.
// Hot loop: per j, two independent (1-2 LDS.128 + STG.128) chains.
// ---------------------------------------------------------------------------
__global__ __launch_bounds__(256)
void relpos_kernel(const int* __restrict__ asym,
                   const int* __restrict__ resi,
                   const int* __restrict__ ent,
                   const int* __restrict__ sym,
                   const int* __restrict__ tok,
                   float* __restrict__ out,
                   int N) {
    extern __shared__ float s_mem[];
    float*    s_tab = s_mem;                                  // 84*128 floats
    unsigned* s_pk  = (unsigned*)(s_mem + S_ROWS * C_Z);      // 2*N entries

    // ---- table copy: 84 rows (a rows as-is, fused rows at g_row = s+72) ----
    {
        const float4* src = (const float4*)g_tab;
        float4*       dst = (float4*)s_tab;
        for (int k = threadIdx.x; k < S_ROWS * 32; k += blockDim.x) {
            int s_row = k >> 5;
            int g_row = (s_row < 66) ? s_row : s_row + 72;
            dst[k] = src[g_row * 32 + (k & 31)];
        }
    }

    const int i0 = blockIdx.x * 2;
    const int i1 = i0 + 1;
    const int a0 = asym[i0], r0_ = resi[i0], e0 = ent[i0], s0 = sym[i0], t0 = tok[i0];
    const int a1 = asym[i1], r1_ = resi[i1], e1 = ent[i1], s1 = sym[i1], t1 = tok[i1];

    // ---- phase 1: per-j packed indices for both i rows (shared j loads) ----
    for (int j = threadIdx.x; j < N; j += blockDim.x) {
        const int aj = __ldg(asym + j);
        const int rj = __ldg(resi + j);
        const int ej = __ldg(ent  + j);
        const int sj = __ldg(sym  + j);
        const int tj = __ldg(tok  + j);
        s_pk[j]         = make_pk(a0, r0_, e0, s0, t0, aj, rj, ej, sj, tj);
        s_pk[N_MAX + j] = make_pk(a1, r1_, e1, s1, t1, aj, rj, ej, sj, tj);
    }
    __syncthreads();

    // ---- phase 2: 2 contiguous j's per warp sweep, 2 output rows per j ----
    const int lane = threadIdx.x & 31;
    const int wid  = threadIdx.x >> 5;
    const float4* t4  = (const float4*)s_tab;                 // [84][32]
    const float4* gb4 = (const float4*)(g_tab + GROW_B * C_Z);
    float* out0 = out + (size_t)i0 * N * C_Z;
    float* out1 = out + (size_t)i1 * N * C_Z;

    for (int j0 = wid * 2; j0 < N; j0 += 16) {
        #pragma unroll
        for (int u = 0; u < 2; u++) {
            const int j = j0 + u;
            const unsigned pk0 = s_pk[j];                     // warp-uniform
            const unsigned pk1 = s_pk[N_MAX + j];             // warp-uniform

            float4 v0 = t4[(pk0 & 127) * 32 + lane];
            float4 v1 = t4[(pk1 & 127) * 32 + lane];

            if (pk0 & PK_TWO) {
                const float4 b = t4[((pk0 >> 7) & 127) * 32 + lane];
                v0.x += b.x; v0.y += b.y; v0.z += b.z; v0.w += b.w;
            }
            if (pk1 & PK_TWO) {
                const float4 b = t4[((pk1 >> 7) & 127) * 32 + lane];
                v1.x += b.x; v1.y += b.y; v1.z += b.z; v1.w += b.w;
            }
            if (pk0 & PK_GB) {                                // rare ~3%
                const float4 g = __ldg(gb4 + (int)(pk0 >> 16) * 32 + lane);
                v0.x += g.x; v0.y += g.y; v0.z += g.z; v0.w += g.w;
            }
            if (pk1 & PK_GB) {                                // rare ~3%
                const float4 g = __ldg(gb4 + (int)(pk1 >> 16) * 32 + lane);
                v1.x += g.x; v1.y += g.y; v1.z += g.z; v1.w += g.w;
            }
            __stcs((float4*)(out0 + (size_t)j * C_Z) + lane, v0);
            __stcs((float4*)(out1 + (size_t)j * C_Z) + lane, v1);
        }
    }
}

extern "C" void kernel_launch(void* const* d_in, const int* in_sizes, int n_in,
                              void* d_out, int out_size) {
    const float* W    = (const float*)d_in[0];
    const int*   asym = (const int*)d_in[1];
    const int*   resi = (const int*)d_in[2];
    const int*   ent  = (const int*)d_in[3];
    const int*   sym  = (const int*)d_in[4];
    const int*   tok  = (const int*)d_in[5];
    float*       out  = (float*)d_out;

    const int N = in_sizes[1];   // 1024

    const int smem = S_ROWS * C_Z * (int)sizeof(float)
                   + 2 * N_MAX * (int)sizeof(unsigned);       // 51200 B
    cudaFuncSetAttribute(relpos_kernel,
                         cudaFuncAttributeMaxDynamicSharedMemorySize, smem);

    build_tables_kernel<<<GTAB_ROWS, C_Z>>>(W);
    relpos_kernel<<<N / 2, 256, smem>>>(asym, resi, ent, sym, tok, out, N);
}

// round 9
// speedup vs baseline: 1.1538x; 1.1538x over previous
#include <cuda_runtime.h>
#include <cstdint>

// Problem constants: R_MAX=32, S_MAX=2, C_Z=128, IN_FEATS=139
#define C_Z      128
#define IN_FEATS 139

// Global fused table layout (rows of 128 floats):
//   [0,66)    a rows:    Wt[dres]
//   [66,132)  b rows:    Wt[66+dtok]
//   [132,138) c rows:    ec<5 ? Wt[132]+Wt[133+ec] : Wt[138]
//   [138,144) bc rows:    b_sent + c_ec             (b_sent = Wt[131])
//   [144,150) abc rows:   a_sent + b_sent + c_ec    (a_sent = Wt[65])
//   [150,156) a32c rows:  a[32] + c_ec              (ri==rj: dres==32)
//   [156,162) a0bc rows:  a[0]  + b_sent + c_ec     (dres clipped to 0)
//   [162,168) a64bc rows: a[64] + b_sent + c_ec     (dres clipped to 64)
#define GROW_B    66
#define GTAB_ROWS 168

// Shared-memory table:
//   [0,66) a | [66,72) bc | [72,78) abc | [78,84) a32c | [84,90) a0bc | [90,96) a64bc
#define S_A      0
#define S_BC     66
#define S_ABC    72
#define S_A32C   78
#define S_A0BC   84
#define S_A64BC  90
#define S_ROWS   96

#define N_MAX   1024

// pk flag bits: pk = r0(7b) | r1(7b)<<7 | TWO<<14 | GB<<15 | dtok<<16
#define PK_TWO  (1u << 14)   // add second smem row r1
#define PK_GB   (1u << 15)   // add global b[dtok] row (rare ri==rj case)

__device__ float g_tab[GTAB_ROWS * C_Z];

// ---------------------------------------------------------------------------
// Pre-kernel: build fused table. W: [C_Z, IN_FEATS] row-major,
// Wt[f][c] = W[c*IN_FEATS + f].
// ---------------------------------------------------------------------------
__global__ void build_tables_kernel(const float* __restrict__ W) {
    int r = blockIdx.x;          // 0..167
    int c = threadIdx.x;         // 0..127
    const float* wc = W + (size_t)c * IN_FEATS;

    float a_sent = wc[65];
    float b_sent = wc[131];

    float v;
    if (r < 132) {
        v = wc[r];                                   // a rows, b rows
    } else {
        int k = (r - 132) % 6;                       // ec class
        float ck = (k < 5) ? (wc[132] + wc[133 + k]) : wc[138];
        if      (r < 138) v = ck;                    // c rows
        else if (r < 144) v = b_sent + ck;           // bc rows
        else if (r < 150) v = a_sent + b_sent + ck;  // abc rows
        else if (r < 156) v = wc[32] + ck;           // a32c rows
        else if (r < 162) v = wc[0]  + b_sent + ck;  // a0bc rows
        else              v = wc[64] + b_sent + ck;  // a64bc rows
    }
    g_tab[r * C_Z + c] = v;
}

// ---------------------------------------------------------------------------
// Main kernel: one block per query row i; 256 threads = 8 warps.
// smem: 96-row table (49KB) + pk (4KB) -> 4 CTAs/SM.
// Hot loop: 1 LDS.128 for ~93% of pairs; ~6-8% take a second LDS.128;
// ~3% add a global b-row. pk's fetched 4-at-a-time via one LDS.128.
// ---------------------------------------------------------------------------
__global__ __launch_bounds__(256)
void relpos_kernel(const int* __restrict__ asym,
                   const int* __restrict__ resi,
                   const int* __restrict__ ent,
                   const int* __restrict__ sym,
                   const int* __restrict__ tok,
                   float* __restrict__ out,
                   int N) {
    extern __shared__ float s_mem[];
    float*    s_tab = s_mem;                                  // 96*128 floats
    unsigned* s_pk  = (unsigned*)(s_mem + S_ROWS * C_Z);      // N entries

    // ---- table copy: 96 rows ----
    {
        const float4* src = (const float4*)g_tab;
        float4*       dst = (float4*)s_tab;
        for (int k = threadIdx.x; k < S_ROWS * 32; k += blockDim.x) {
            int s_row = k >> 5;
            int g_row = (s_row < 66) ? s_row : s_row + 72;    // fused at g 138..167
            dst[k] = src[g_row * 32 + (k & 31)];
        }
    }

    const int i = blockIdx.x;
    const int ai = asym[i], ri = resi[i], ei = ent[i], si = sym[i], ti = tok[i];

    // ---- phase 1: per-j packed indices (once per block) ----
    for (int j = threadIdx.x; j < N; j += blockDim.x) {
        const int aj = __ldg(asym + j);
        const int rj = __ldg(resi + j);
        const int ej = __ldg(ent  + j);
        const int sj = __ldg(sym  + j);
        const int tj = __ldg(tok  + j);

        int ec = (ei == ej) ? min(max(si - sj + 2, 0), 4) : 5;

        unsigned pk;
        if (ai != aj) {
            pk = (unsigned)(S_ABC + ec);                       // 1 row
        } else if (ri != rj) {
            int dres = min(max(ri - rj + 32, 0), 64);
            if (dres == 0)
                pk = (unsigned)(S_A0BC + ec);                  // 1 fused row
            else if (dres == 64)
                pk = (unsigned)(S_A64BC + ec);                 // 1 fused row
            else
                pk = (unsigned)(S_A + dres)
                   | ((unsigned)(S_BC + ec) << 7) | PK_TWO;    // 2 rows
        } else {
            // dres == 32 exactly; a[32] folded into a32c[ec]; b row global.
            int dtok = min(max(ti - tj + 32, 0), 64);
            pk = (unsigned)(S_A32C + ec)
               | PK_GB | ((unsigned)dtok << 16);               // 1 row + global
        }
        s_pk[j] = pk;
    }
    __syncthreads();

    // ---- phase 2: 4 contiguous j's per warp sweep; pk via one LDS.128 ----
    const int lane = threadIdx.x & 31;
    const int wid  = threadIdx.x >> 5;
    const float4* t4  = (const float4*)s_tab;                  // [96][32]
    const float4* gb4 = (const float4*)(g_tab + GROW_B * C_Z);
    float* out_i = out + (size_t)i * N * C_Z;

    for (int j0 = wid * 4; j0 < N; j0 += 32) {
        const uint4 pkv = *(const uint4*)(s_pk + j0);          // broadcast LDS.128
        unsigned pks[4] = {pkv.x, pkv.y, pkv.z, pkv.w};

        float4 v[4];
        #pragma unroll
        for (int u = 0; u < 4; u++)
            v[u] = t4[(pks[u] & 127) * 32 + lane];

        #pragma unroll
        for (int u = 0; u < 4; u++) {
            if (pks[u] & PK_TWO) {                             // ~6-8%, warp-uniform
                const float4 b = t4[((pks[u] >> 7) & 127) * 32 + lane];
                v[u].x += b.x; v[u].y += b.y; v[u].z += b.z; v[u].w += b.w;
            }
            if (pks[u] & PK_GB) {                              // ~3%, warp-uniform
                const float4 g = __ldg(gb4 + (int)(pks[u] >> 16) * 32 + lane);
                v[u].x += g.x; v[u].y += g.y; v[u].z += g.z; v[u].w += g.w;
            }
        }

        #pragma unroll
        for (int u = 0; u < 4; u++)
            __stcs((float4*)(out_i + (size_t)(j0 + u) * C_Z) + lane, v[u]);
    }
}

extern "C" void kernel_launch(void* const* d_in, const int* in_sizes, int n_in,
                              void* d_out, int out_size) {
    const float* W    = (const float*)d_in[0];
    const int*   asym = (const int*)d_in[1];
    const int*   resi = (const int*)d_in[2];
    const int*   ent  = (const int*)d_in[3];
    const int*   sym  = (const int*)d_in[4];
    const int*   tok  = (const int*)d_in[5];
    float*       out  = (float*)d_out;

    const int N = in_sizes[1];   // 1024

    const int smem = S_ROWS * C_Z * (int)sizeof(float)
                   + N_MAX * (int)sizeof(unsigned);            // 53248 B
    cudaFuncSetAttribute(relpos_kernel,
                         cudaFuncAttributeMaxDynamicSharedMemorySize, smem);

    build_tables_kernel<<<GTAB_ROWS, C_Z>>>(W);
    relpos_kernel<<<N, 256, smem>>>(asym, resi, ent, sym, tok, out, N);
}

// round 10
// speedup vs baseline: 1.1797x; 1.0225x over previous
#include <cuda_runtime.h>
#include <cstdint>

// Problem constants: R_MAX=32, S_MAX=2, C_Z=128, IN_FEATS=139
#define C_Z      128
#define IN_FEATS 139

// Global fused table layout (rows of 128 floats):
//   [0,66)    a rows:    Wt[dres]
//   [66,132)  b rows:    Wt[66+dtok]
//   [132,138) c rows:    ec<5 ? Wt[132]+Wt[133+ec] : Wt[138]
//   [138,144) bc rows:   b_sent + c_ec              (b_sent = Wt[131])
//   [144,150) abc rows:  a_sent + b_sent + c_ec     (a_sent = Wt[65])
//   [150,156) a32c rows: a[32] + c_ec               (ri==rj: dres==32)
#define GROW_B    66
#define GTAB_ROWS 156

// Shared-memory table (a rows as-is; fused rows at global_row - 72):
//   [0,66) a | [66,72) bc | [72,78) abc | [78,84) a32c
#define S_A     0
#define S_BC    66
#define S_ABC   72
#define S_A32C  78
#define S_ROWS  84

#define N_MAX   1024
#define NH_MAX  (N_MAX / 2)

// pk (u16): r0(7b) | r1val(7b)<<7 | TWO<<14 | GB<<15
//   case1: r1val = bc row index; case2 (GB): r1val = dtok (b row = GROW_B+dtok)
#define PK_TWO  (1u << 14)
#define PK_GB   (1u << 15)

__device__ float g_tab[GTAB_ROWS * C_Z];

// ---------------------------------------------------------------------------
// Pre-kernel: build fused table. W: [C_Z, IN_FEATS] row-major,
// Wt[f][c] = W[c*IN_FEATS + f].
// ---------------------------------------------------------------------------
__global__ void build_tables_kernel(const float* __restrict__ W) {
    int r = blockIdx.x;          // 0..155
    int c = threadIdx.x;         // 0..127
    const float* wc = W + (size_t)c * IN_FEATS;

    float a_sent = wc[65];
    float b_sent = wc[131];
    float a32    = wc[32];

    float v;
    if (r < 132) {
        v = wc[r];                                   // a rows, b rows
    } else {
        int k = (r - 132) % 6;                       // ec class
        float ck = (k < 5) ? (wc[132] + wc[133 + k]) : wc[138];
        if      (r < 138) v = ck;                    // c rows
        else if (r < 144) v = b_sent + ck;           // bc rows
        else if (r < 150) v = a_sent + b_sent + ck;  // abc rows
        else              v = a32 + ck;              // a32c rows
    }
    g_tab[r * C_Z + c] = v;
}

// ---------------------------------------------------------------------------
// Main kernel: TWO blocks per query row i; block handles half the j-range.
// grid = 2N = 2048 (fine-grained drain), smem = 84-row table (43K) + 1K pk
// -> 5 CTAs/SM. Hot loop: 1 LDS.128 (75%) or 2 (25%), warp-uniform branch,
// rare (~3%) global b-row, STG.128 streaming store.
// ---------------------------------------------------------------------------
__global__ __launch_bounds__(256, 5)
void relpos_kernel(const int* __restrict__ asym,
                   const int* __restrict__ resi,
                   const int* __restrict__ ent,
                   const int* __restrict__ sym,
                   const int* __restrict__ tok,
                   float* __restrict__ out,
                   int N) {
    extern __shared__ float s_mem[];
    float*          s_tab = s_mem;                                 // 84*128 floats
    unsigned short* s_pk  = (unsigned short*)(s_mem + S_ROWS * C_Z); // NH entries

    // ---- table copy: 84 rows (a rows as-is, fused rows at g_row = s+72) ----
    {
        const float4* src = (const float4*)g_tab;
        float4*       dst = (float4*)s_tab;
        for (int k = threadIdx.x; k < S_ROWS * 32; k += blockDim.x) {
            int s_row = k >> 5;
            int g_row = (s_row < 66) ? s_row : s_row + 72;
            dst[k] = src[g_row * 32 + (k & 31)];
        }
    }

    const int NH    = N >> 1;
    const int i     = blockIdx.x >> 1;
    const int jbase = (blockIdx.x & 1) * NH;

    const int ai = asym[i], ri = resi[i], ei = ent[i], si = sym[i], ti = tok[i];

    // ---- phase 1: packed indices for this block's half of j ----
    for (int jj = threadIdx.x; jj < NH; jj += blockDim.x) {
        const int j = jbase + jj;
        const int aj = __ldg(asym + j);
        const int rj = __ldg(resi + j);
        const int ej = __ldg(ent  + j);
        const int sj = __ldg(sym  + j);
        const int tj = __ldg(tok  + j);

        int ec = (ei == ej) ? min(max(si - sj + 2, 0), 4) : 5;

        unsigned pk;
        if (ai != aj) {
            pk = (unsigned)(S_ABC + ec);                       // 1 row
        } else if (ri != rj) {
            int dres = min(max(ri - rj + 32, 0), 64);
            pk = (unsigned)(S_A + dres)
               | ((unsigned)(S_BC + ec) << 7) | PK_TWO;        // 2 rows
        } else {
            // dres == 32 exactly; a[32] folded into a32c[ec]; b row global.
            int dtok = min(max(ti - tj + 32, 0), 64);
            pk = (unsigned)(S_A32C + ec)
               | ((unsigned)dtok << 7) | PK_GB;                // 1 row + global
        }
        s_pk[jj] = (unsigned short)pk;
    }
    __syncthreads();

    // ---- phase 2: 4 contiguous j's per warp sweep; pk via one LDS.64 ----
    const int lane = threadIdx.x & 31;
    const int wid  = threadIdx.x >> 5;
    const float4* t4  = (const float4*)s_tab;                  // [84][32]
    const float4* gb4 = (const float4*)(g_tab + GROW_B * C_Z);
    float* out_b = out + ((size_t)i * N + jbase) * C_Z;

    for (int jj0 = wid * 4; jj0 < NH; jj0 += 32) {
        const ushort4 pkv = *(const ushort4*)(s_pk + jj0);     // broadcast LDS.64
        unsigned pks[4] = {pkv.x, pkv.y, pkv.z, pkv.w};

        float4 v[4];
        #pragma unroll
        for (int u = 0; u < 4; u++)
            v[u] = t4[(pks[u] & 127) * 32 + lane];

        #pragma unroll
        for (int u = 0; u < 4; u++) {
            const int r1v = (int)((pks[u] >> 7) & 127);
            if (pks[u] & PK_TWO) {                             // ~25%, warp-uniform
                const float4 b = t4[r1v * 32 + lane];
                v[u].x += b.x; v[u].y += b.y; v[u].z += b.z; v[u].w += b.w;
            }
            if (pks[u] & PK_GB) {                              // ~3%, warp-uniform
                const float4 g = __ldg(gb4 + r1v * 32 + lane);
                v[u].x += g.x; v[u].y += g.y; v[u].z += g.z; v[u].w += g.w;
            }
        }

        #pragma unroll
        for (int u = 0; u < 4; u++)
            __stcs((float4*)(out_b + (size_t)(jj0 + u) * C_Z) + lane, v[u]);
    }
}

extern "C" void kernel_launch(void* const* d_in, const int* in_sizes, int n_in,
                              void* d_out, int out_size) {
    const float* W    = (const float*)d_in[0];
    const int*   asym = (const int*)d_in[1];
    const int*   resi = (const int*)d_in[2];
    const int*   ent  = (const int*)d_in[3];
    const int*   sym  = (const int*)d_in[4];
    const int*   tok  = (const int*)d_in[5];
    float*       out  = (float*)d_out;

    const int N = in_sizes[1];   // 1024

    const int smem = S_ROWS * C_Z * (int)sizeof(float)
                   + NH_MAX * (int)sizeof(unsigned short);     // 44032 B
    cudaFuncSetAttribute(relpos_kernel,
                         cudaFuncAttributeMaxDynamicSharedMemorySize, smem);

    build_tables_kernel<<<GTAB_ROWS, C_Z>>>(W);
    relpos_kernel<<<2 * N, 256, smem>>>(asym, resi, ent, sym, tok, out, N);
}